// round 14
// baseline (speedup 1.0000x reference)
#include <cuda_runtime.h>
#include <cstdint>

// ---------------------------------------------------------------------------
// RASP pairwise score — R13 bests + latency-hidden work stealing.
//  R13 evidence: pair 32.7us, issue 66.7% (floor ~22us); 2352 blocks / 12 per
//  SM = 1.33 waves -> ~3-4us tail. R11's stealing failed because the chunk
//  ATOMG sat on the critical path; R14 prefetches chunk n+1 during chunk n.
//  Also: pot base pointer pre-offset by ti21 (-1 IADD/body).
// ---------------------------------------------------------------------------

static constexpr int N_MAX   = 6144;
static constexpr int T_TYPES = 85;
static constexpr int TJ      = 128;
static constexpr int HJ      = 64;
static constexpr int BLOCK_T = 128;
static constexpr int NTILES  = N_MAX / TJ;                  // 48
static constexpr int NWORK   = NTILES * (NTILES + 1) / 2;   // 1176
static constexpr int NCHUNK  = NWORK * 2;                   // 2352
static constexpr int GRID_P  = 12 * 148;                    // 1776 = one wave
static constexpr int KSTRIDE = 85 * 85 * 21;                // 151725

__device__ float4 g_tmp[N_MAX];     // packed, unsorted: {x,y,z,(t<<22)|(rank<<9)|r}
__device__ float4 g_atoms[N_MAX];   // sorted coords
__device__ int4   g_meta[N_MAX];    // sorted {res, t*21, t*1764, unused}
__device__ int    g_hist[T_TYPES];  // zero-init; scatter re-zeroes per replay
__device__ float  g_es;             // zero-init; last pair block resets
__device__ unsigned int g_ticket;
__device__ unsigned int g_work;     // chunk counter; last pair block resets

// ---------------------------------------------------------------------------
// Packed f32x2 helpers (Blackwell FADD2/FFMA2; ptxas won't auto-fuse).
__device__ __forceinline__ unsigned long long pk2(float a, float b) {
    unsigned long long r;
    asm("mov.b64 %0, {%1, %2};" : "=l"(r) : "f"(a), "f"(b));
    return r;
}
__device__ __forceinline__ unsigned long long add2(unsigned long long a,
                                                   unsigned long long b) {
    unsigned long long r;
    asm("add.rn.f32x2 %0, %1, %2;" : "=l"(r) : "l"(a), "l"(b));
    return r;
}
__device__ __forceinline__ unsigned long long mul2(unsigned long long a,
                                                   unsigned long long b) {
    unsigned long long r;
    asm("mul.rn.f32x2 %0, %1, %2;" : "=l"(r) : "l"(a), "l"(b));
    return r;
}
__device__ __forceinline__ unsigned long long fma2(unsigned long long a,
                                                   unsigned long long b,
                                                   unsigned long long c) {
    unsigned long long r;
    asm("fma.rn.f32x2 %0, %1, %2, %3;" : "=l"(r) : "l"(a), "l"(b), "l"(c));
    return r;
}
__device__ __forceinline__ void upk2(unsigned long long v, float& lo, float& hi) {
    asm("mov.b64 {%0, %1}, %2;" : "=f"(lo), "=f"(hi) : "l"(v));
}

// ---------------------------------------------------------------------------
// Phase 1 (full chip): load, poison, rank within type via atomic histogram.
__global__ void pack_kernel(const float* __restrict__ coords,
                            const int*   __restrict__ res_ids,
                            const int*   __restrict__ types,
                            int n)
{
    int i = blockIdx.x * blockDim.x + threadIdx.x;
    if (i >= N_MAX) return;

    float x = 0.f, y = 0.f, z = 0.f;
    int t = -1, r = 0;
    if (i < n) {
        x = coords[3 * i + 0];
        y = coords[3 * i + 1];
        z = coords[3 * i + 2];
        t = types[i];
        r = res_ids[i];
    }
    if (t < 0) {
        // Poison: spacing 32 > 20 also excludes poisoned-poisoned pairs.
        float p = 1.0e6f + 32.0f * (float)i;
        x = p; y = p; z = p;
        t = 0;
    }
    int rank = atomicAdd(&g_hist[t], 1);            // 13 bits
    int w = (t << 22) | (rank << 9) | r;            // 7 | 13 | 9 bits
    g_tmp[i] = make_float4(x, y, z, __int_as_float(w));
}

// ---------------------------------------------------------------------------
// Phase 2 (full chip, 48 blocks): per-block warp scan of the 85-bin histogram
// (redundant, ~50 cyc) then scatter into type-sorted order. Block 0 re-zeroes
// g_hist afterwards for the next graph replay.
__global__ __launch_bounds__(BLOCK_T)
void scatter_kernel()
{
    __shared__ int s_base[T_TYPES];
    const int tid = threadIdx.x;

    if (tid < 32) {
        int lane = tid;
        int h0 = (lane < T_TYPES)      ? g_hist[lane]      : 0;
        int h1 = (lane + 32 < T_TYPES) ? g_hist[lane + 32] : 0;
        int h2 = (lane + 64 < T_TYPES) ? g_hist[lane + 64] : 0;
        int s0 = h0, s1 = h1, s2 = h2;
#pragma unroll
        for (int o = 1; o < 32; o <<= 1) {
            int t0 = __shfl_up_sync(0xffffffffu, s0, o);
            int t1 = __shfl_up_sync(0xffffffffu, s1, o);
            int t2 = __shfl_up_sync(0xffffffffu, s2, o);
            if (lane >= o) { s0 += t0; s1 += t1; s2 += t2; }
        }
        int tot0 = __shfl_sync(0xffffffffu, s0, 31);
        int tot1 = __shfl_sync(0xffffffffu, s1, 31);
        s1 += tot0;
        s2 += tot0 + tot1;
        if (lane < T_TYPES)      s_base[lane]      = s0 - h0;   // exclusive
        if (lane + 32 < T_TYPES) s_base[lane + 32] = s1 - h1;
        if (lane + 64 < T_TYPES) s_base[lane + 64] = s2 - h2;
    }
    __syncthreads();

    const int i = blockIdx.x * BLOCK_T + tid;
    float4 a = g_tmp[i];
    int w = __float_as_int(a.w);
    int t    = w >> 22;
    int rank = (w >> 9) & 0x1FFF;
    int r    = w & 0x1FF;
    int pos = s_base[t] + rank;
    g_atoms[pos] = make_float4(a.x, a.y, a.z, 0.f);
    g_meta[pos]  = make_int4(r, t * 21, t * 1764, 0);

    // Reset histogram for the next replay (all scans above already read it).
    if (blockIdx.x == 0 && tid < T_TYPES) g_hist[tid] = 0;
}

// ---------------------------------------------------------------------------
// Persistent pair kernel: 1776 blocks (one resident wave) steal 2352 chunks;
// the NEXT chunk id is prefetched at the top of each chunk so the ATOMG
// latency hides under the ~8K-cycle chunk body.
__global__ __launch_bounds__(BLOCK_T, 12)   // cap regs ~40 (measured best)
void pair_kernel(const float* __restrict__ pot, float* __restrict__ out)
{
    __shared__ float2 sXn[HJ / 2], sYn[HJ / 2], sZn[HJ / 2];
    __shared__ int4   sM[HJ];
    __shared__ int    s_next;
    __shared__ float  wes[BLOCK_T / 32];

    const int tid = threadIdx.x;
    const float* potm1 = pot - KSTRIDE;     // kc in [1,6] re-biases k slot
    float es_blk = 0.f, cn_blk = 0.f;

    if (tid == 0) s_next = (int)atomicAdd(&g_work, 1u);
    __syncthreads();
    int c = s_next;

    while (c < NCHUNK) {
        if (tid == 0) s_next = (int)atomicAdd(&g_work, 1u);   // prefetch n+1

        // Triangular decode: bid -> (iT, jT), jT >= iT.
        const int bid = c >> 1;
        int iT = (int)((97.0f - sqrtf(9409.0f - 8.0f * (float)bid)) * 0.5f);
#define TRI_S(i) (((97 * (i)) - (i) * (i)) / 2)
        while (TRI_S(iT + 1) <= bid) iT++;
        while (TRI_S(iT) > bid) iT--;
        const int jT = iT + (bid - TRI_S(iT));
#undef TRI_S
        const int jbase = jT * TJ + (c & 1) * HJ;

        // Planar NEGATED j coords (packed adds replace subs) + meta.
        if (tid < HJ) {
            float4 aj = g_atoms[jbase + tid];
            ((float*)sXn)[tid] = -aj.x;
            ((float*)sYn)[tid] = -aj.y;
            ((float*)sZn)[tid] = -aj.z;
        } else {
            sM[tid - HJ] = g_meta[jbase + tid - HJ];
        }
        __syncthreads();    // smem tiles ready; also publishes s_next

        const int ig = iT * TJ + tid;
        const float4 a  = g_atoms[ig];
        const int4   im = g_meta [ig];
        const unsigned long long xi2 = pk2(a.x, a.x);
        const unsigned long long yi2 = pk2(a.y, a.y);
        const unsigned long long zi2 = pk2(a.z, a.z);
        const int ri = im.x, ti1764 = im.z;
        const float* pbase = potm1 + im.y;  // ti21 folded into base pointer
        const int relJ = jbase - ig;        // j_global = relJ + ig + J

        float es0 = 0.f, es1 = 0.f;
        float cn0 = 0.f, cn1 = 0.f;

    // Gather always in-bounds: kc in [1,6] (potm1 base), d0i clamped to 19.
    // (ti,tj) ORIGINAL-index order == res order for contributing pairs
    // (res_ids sorted by orig index; sep>2 => ri!=rj) -> sign of sepd.
    // Index identity: first*1785 + second*21 = (ti21+tj21) + first*1764,
    // with ti21 hoisted into pbase.
#define TAIL(DIST, MM, JOFF, ES, CN)                                           \
    {                                                                          \
        int sepd = ri - MM.x;                                                  \
        int sep  = sepd < 0 ? -sepd : sepd;                                    \
        bool ok = (sep > 2) && (DIST < 20.0f);                                 \
        if (CHECK_IJ) ok = ok && ((JOFF) + relJ > 0);                          \
        int kc  = min(max(sep, 1), 6);                                         \
        int d0i = min((int)DIST, 19);                                          \
        float alpha = DIST - (float)d0i;                                       \
        int idx = kc * KSTRIDE + MM.y                                          \
                + ((sepd < 0) ? ti1764 : MM.z) + d0i;                          \
        float e0 = __ldg(pbase + idx);                                         \
        float e1 = __ldg(pbase + idx + 1);                                     \
        float val = fmaf(alpha, e1 - e0, e0);                                  \
        if (ok) { ES += val; CN += 1.0f; }                                     \
    }

#define PAIR2(P)                                                               \
    {                                                                          \
        unsigned long long xn = ((const unsigned long long*)sXn)[P];           \
        unsigned long long yn = ((const unsigned long long*)sYn)[P];           \
        unsigned long long zn = ((const unsigned long long*)sZn)[P];           \
        int4 m0 = sM[2 * (P)];                                                 \
        int4 m1 = sM[2 * (P) + 1];                                             \
        unsigned long long dx2 = add2(xi2, xn);                                \
        unsigned long long dy2 = add2(yi2, yn);                                \
        unsigned long long dz2 = add2(zi2, zn);                                \
        unsigned long long d22 = mul2(dx2, dx2);                               \
        d22 = fma2(dy2, dy2, d22);                                             \
        d22 = fma2(dz2, dz2, d22);                                             \
        float d2a, d2b;                                                        \
        upk2(d22, d2a, d2b);                                                   \
        float da, db;                                                          \
        asm("sqrt.approx.f32 %0, %1;" : "=f"(da) : "f"(d2a));                  \
        asm("sqrt.approx.f32 %0, %1;" : "=f"(db) : "f"(d2b));                  \
        TAIL(da, m0, 2 * (P),     es0, cn0)                                    \
        TAIL(db, m1, 2 * (P) + 1, es1, cn1)                                    \
    }

        if (iT != jT) {
#define CHECK_IJ false
#pragma unroll 4
            for (int p = 0; p < HJ / 2; p++) PAIR2(p)
#undef CHECK_IJ
        } else {
#define CHECK_IJ true
#pragma unroll 4
            for (int p = 0; p < HJ / 2; p++) PAIR2(p)
#undef CHECK_IJ
        }
#undef PAIR2
#undef TAIL

        es_blk += es0 + es1;
        cn_blk += cn0 + cn1;

        c = s_next;         // published by the fill barrier above
        __syncthreads();    // everyone done with smem + s_next before refill
    }

    // Fold -2.7 per contributing pair via exact per-thread count (<=128).
    float es = fmaf(-2.7f, cn_blk, es_blk);
#pragma unroll
    for (int o = 16; o > 0; o >>= 1)
        es += __shfl_down_sync(0xffffffffu, es, o);

    if ((tid & 31) == 0) wes[tid >> 5] = es;
    __syncthreads();

    if (tid == 0) {
        float e = 0.f;
#pragma unroll
        for (int w = 0; w < BLOCK_T / 32; w++) e += wes[w];

        atomicAdd(&g_es, e);
        __threadfence();
        unsigned int t = atomicAdd(&g_ticket, 1u);
        if (t == (unsigned int)(GRID_P - 1)) {
            // All blocks ticketed => no further g_work grabs anywhere.
            __threadfence();
            *out = *(volatile float*)&g_es;
            g_es = 0.0f;          // reset for next graph replay
            g_ticket = 0u;
            g_work = 0u;
        }
    }
}

// ---------------------------------------------------------------------------
extern "C" void kernel_launch(void* const* d_in, const int* in_sizes, int n_in,
                              void* d_out, int out_size)
{
    const float* coords  = (const float*)d_in[0];
    const int*   res_ids = (const int*)  d_in[1];
    const int*   types   = (const int*)  d_in[2];
    const float* pot     = (const float*)d_in[3];
    float*       out     = (float*)d_out;

    int n = in_sizes[1];
    if (n > N_MAX) n = N_MAX;

    pack_kernel<<<N_MAX / 128, 128>>>(coords, res_ids, types, n);
    scatter_kernel<<<N_MAX / 128, 128>>>();

    pair_kernel<<<GRID_P, BLOCK_T>>>(pot, out);
}

// round 15
// speedup vs baseline: 1.2901x; 1.2901x over previous
#include <cuda_runtime.h>
#include <cstdint>

// ---------------------------------------------------------------------------
// RASP pairwise score — R13 (proven 36.9us) + two micro-diets.
//  R14 evidence: persistent/stealing regressed again (45.5) -> retired.
//  R15: static 2352-block grid (R13) + (a) pot base pre-offset by ti21,
//  (b) float-domain bin path (FMNMX+FRND+FADD+F2I replaces 5-op int path).
// ---------------------------------------------------------------------------

static constexpr int N_MAX   = 6144;
static constexpr int T_TYPES = 85;
static constexpr int TJ      = 128;
static constexpr int HJ      = 64;
static constexpr int BLOCK_T = 128;
static constexpr int NTILES  = N_MAX / TJ;                  // 48
static constexpr int NWORK   = NTILES * (NTILES + 1) / 2;   // 1176
static constexpr int NBLK    = NWORK * 2;                   // 2352
static constexpr int KSTRIDE = 85 * 85 * 21;                // 151725

__device__ float4 g_tmp[N_MAX];     // packed, unsorted: {x,y,z,(t<<22)|(rank<<9)|r}
__device__ float4 g_atoms[N_MAX];   // sorted coords
__device__ int4   g_meta[N_MAX];    // sorted {res, t*21, t*1764, unused}
__device__ int    g_hist[T_TYPES];  // zero-init; scatter re-zeroes per replay
__device__ float  g_es;             // zero-init; last pair block resets
__device__ unsigned int g_ticket;

// ---------------------------------------------------------------------------
// Packed f32x2 helpers (Blackwell FADD2/FFMA2; ptxas won't auto-fuse).
__device__ __forceinline__ unsigned long long pk2(float a, float b) {
    unsigned long long r;
    asm("mov.b64 %0, {%1, %2};" : "=l"(r) : "f"(a), "f"(b));
    return r;
}
__device__ __forceinline__ unsigned long long add2(unsigned long long a,
                                                   unsigned long long b) {
    unsigned long long r;
    asm("add.rn.f32x2 %0, %1, %2;" : "=l"(r) : "l"(a), "l"(b));
    return r;
}
__device__ __forceinline__ unsigned long long mul2(unsigned long long a,
                                                   unsigned long long b) {
    unsigned long long r;
    asm("mul.rn.f32x2 %0, %1, %2;" : "=l"(r) : "l"(a), "l"(b));
    return r;
}
__device__ __forceinline__ unsigned long long fma2(unsigned long long a,
                                                   unsigned long long b,
                                                   unsigned long long c) {
    unsigned long long r;
    asm("fma.rn.f32x2 %0, %1, %2, %3;" : "=l"(r) : "l"(a), "l"(b), "l"(c));
    return r;
}
__device__ __forceinline__ void upk2(unsigned long long v, float& lo, float& hi) {
    asm("mov.b64 {%0, %1}, %2;" : "=f"(lo), "=f"(hi) : "l"(v));
}

// ---------------------------------------------------------------------------
// Phase 1 (full chip): load, poison, rank within type via atomic histogram.
__global__ void pack_kernel(const float* __restrict__ coords,
                            const int*   __restrict__ res_ids,
                            const int*   __restrict__ types,
                            int n)
{
    int i = blockIdx.x * blockDim.x + threadIdx.x;
    if (i >= N_MAX) return;

    float x = 0.f, y = 0.f, z = 0.f;
    int t = -1, r = 0;
    if (i < n) {
        x = coords[3 * i + 0];
        y = coords[3 * i + 1];
        z = coords[3 * i + 2];
        t = types[i];
        r = res_ids[i];
    }
    if (t < 0) {
        // Poison: spacing 32 > 20 also excludes poisoned-poisoned pairs.
        float p = 1.0e6f + 32.0f * (float)i;
        x = p; y = p; z = p;
        t = 0;
    }
    int rank = atomicAdd(&g_hist[t], 1);            // 13 bits
    int w = (t << 22) | (rank << 9) | r;            // 7 | 13 | 9 bits
    g_tmp[i] = make_float4(x, y, z, __int_as_float(w));
}

// ---------------------------------------------------------------------------
// Phase 2 (full chip, 48 blocks): per-block warp scan of the 85-bin histogram
// (redundant, ~50 cyc) then scatter into type-sorted order. Block 0 re-zeroes
// g_hist afterwards for the next graph replay.
__global__ __launch_bounds__(BLOCK_T)
void scatter_kernel()
{
    __shared__ int s_base[T_TYPES];
    const int tid = threadIdx.x;

    if (tid < 32) {
        int lane = tid;
        int h0 = (lane < T_TYPES)      ? g_hist[lane]      : 0;
        int h1 = (lane + 32 < T_TYPES) ? g_hist[lane + 32] : 0;
        int h2 = (lane + 64 < T_TYPES) ? g_hist[lane + 64] : 0;
        int s0 = h0, s1 = h1, s2 = h2;
#pragma unroll
        for (int o = 1; o < 32; o <<= 1) {
            int t0 = __shfl_up_sync(0xffffffffu, s0, o);
            int t1 = __shfl_up_sync(0xffffffffu, s1, o);
            int t2 = __shfl_up_sync(0xffffffffu, s2, o);
            if (lane >= o) { s0 += t0; s1 += t1; s2 += t2; }
        }
        int tot0 = __shfl_sync(0xffffffffu, s0, 31);
        int tot1 = __shfl_sync(0xffffffffu, s1, 31);
        s1 += tot0;
        s2 += tot0 + tot1;
        if (lane < T_TYPES)      s_base[lane]      = s0 - h0;   // exclusive
        if (lane + 32 < T_TYPES) s_base[lane + 32] = s1 - h1;
        if (lane + 64 < T_TYPES) s_base[lane + 64] = s2 - h2;
    }
    __syncthreads();

    const int i = blockIdx.x * BLOCK_T + tid;
    float4 a = g_tmp[i];
    int w = __float_as_int(a.w);
    int t    = w >> 22;
    int rank = (w >> 9) & 0x1FFF;
    int r    = w & 0x1FF;
    int pos = s_base[t] + rank;
    g_atoms[pos] = make_float4(a.x, a.y, a.z, 0.f);
    g_meta[pos]  = make_int4(r, t * 21, t * 1764, 0);

    // Reset histogram for the next replay (all scans above already read it).
    if (blockIdx.x == 0 && tid < T_TYPES) g_hist[tid] = 0;
}

// ---------------------------------------------------------------------------
__global__ __launch_bounds__(BLOCK_T, 12)   // cap regs ~40 (measured best)
void pair_kernel(const float* __restrict__ pot, float* __restrict__ out)
{
    // Triangular decode on blockIdx.x: bid -> (iT, jT), jT >= iT.
    const int bid = blockIdx.x;
    int iT = (int)((97.0f - sqrtf(9409.0f - 8.0f * (float)bid)) * 0.5f);
#define TRI_S(i) (((97 * (i)) - (i) * (i)) / 2)
    while (TRI_S(iT + 1) <= bid) iT++;
    while (TRI_S(iT) > bid) iT--;
    const int jT = iT + (bid - TRI_S(iT));
#undef TRI_S
    const int hbase = blockIdx.y * HJ;
    const int jbase = jT * TJ + hbase;

    // Planar NEGATED j coords (packed adds replace subs) + meta.
    __shared__ float2 sXn[HJ / 2], sYn[HJ / 2], sZn[HJ / 2];
    __shared__ int4   sM[HJ];
    const int tid = threadIdx.x;
    if (tid < HJ) {
        float4 a = g_atoms[jbase + tid];
        ((float*)sXn)[tid] = -a.x;
        ((float*)sYn)[tid] = -a.y;
        ((float*)sZn)[tid] = -a.z;
    } else {
        sM[tid - HJ] = g_meta[jbase + tid - HJ];
    }
    __syncthreads();

    const int ig = iT * TJ + tid;
    const float4 a  = g_atoms[ig];
    const int4   im = g_meta [ig];
    const unsigned long long xi2 = pk2(a.x, a.x);
    const unsigned long long yi2 = pk2(a.y, a.y);
    const unsigned long long zi2 = pk2(a.z, a.z);
    const int ri = im.x, ti1764 = im.z;
    const float* pbase = pot - KSTRIDE + im.y;  // ti21 + k-rebias folded in
    const int relJ = jbase - ig;                // j_global = relJ + ig + J

    float es0 = 0.f, es1 = 0.f;
    float cn0 = 0.f, cn1 = 0.f;

    // Gather always in-bounds: kc in [1,6] (rebased), d0i <= 19 via the
    // float clamp (dc <= 19.9999 -> floor <= 19).
    // (ti,tj) ORIGINAL-index order == res order for contributing pairs
    // (res_ids sorted by orig index; sep>2 => ri!=rj) -> sign of sepd.
    // Index identity: first*1785 + second*21 = (ti21+tj21) + first*1764,
    // ti21 hoisted into pbase. Contributing pairs have dist<20 => dc==dist
    // (float-exact below 19.9999; the [19.9999,20) sliver still floors to 19).
#define TAIL(DIST, MM, JOFF, ES, CN)                                           \
    {                                                                          \
        int sepd = ri - MM.x;                                                  \
        int sep  = sepd < 0 ? -sepd : sepd;                                    \
        bool ok = (sep > 2) && (DIST < 20.0f);                                 \
        if (CHECK_IJ) ok = ok && ((JOFF) + relJ > 0);                          \
        int kc  = min(max(sep, 1), 6);                                         \
        float dc  = fminf(DIST, 19.999999f);                                   \
        float d0f = floorf(dc);                                                \
        float alpha = dc - d0f;                                                \
        int idx = kc * KSTRIDE + MM.y                                          \
                + ((sepd < 0) ? ti1764 : MM.z) + (int)d0f;                     \
        float e0 = __ldg(pbase + idx);                                         \
        float e1 = __ldg(pbase + idx + 1);                                     \
        float val = fmaf(alpha, e1 - e0, e0);                                  \
        if (ok) { ES += val; CN += 1.0f; }                                     \
    }

#define PAIR2(P)                                                               \
    {                                                                          \
        unsigned long long xn = ((const unsigned long long*)sXn)[P];           \
        unsigned long long yn = ((const unsigned long long*)sYn)[P];           \
        unsigned long long zn = ((const unsigned long long*)sZn)[P];           \
        int4 m0 = sM[2 * (P)];                                                 \
        int4 m1 = sM[2 * (P) + 1];                                             \
        unsigned long long dx2 = add2(xi2, xn);                                \
        unsigned long long dy2 = add2(yi2, yn);                                \
        unsigned long long dz2 = add2(zi2, zn);                                \
        unsigned long long d22 = mul2(dx2, dx2);                               \
        d22 = fma2(dy2, dy2, d22);                                             \
        d22 = fma2(dz2, dz2, d22);                                             \
        float d2a, d2b;                                                        \
        upk2(d22, d2a, d2b);                                                   \
        float da, db;                                                          \
        asm("sqrt.approx.f32 %0, %1;" : "=f"(da) : "f"(d2a));                  \
        asm("sqrt.approx.f32 %0, %1;" : "=f"(db) : "f"(d2b));                  \
        TAIL(da, m0, 2 * (P),     es0, cn0)                                    \
        TAIL(db, m1, 2 * (P) + 1, es1, cn1)                                    \
    }

    if (iT != jT) {
#define CHECK_IJ false
#pragma unroll 4
        for (int p = 0; p < HJ / 2; p++) PAIR2(p)
#undef CHECK_IJ
    } else {
#define CHECK_IJ true
#pragma unroll 4
        for (int p = 0; p < HJ / 2; p++) PAIR2(p)
#undef CHECK_IJ
    }
#undef PAIR2
#undef TAIL

    // Fold the -2.7 per contributing pair via exact per-thread count (<=64).
    float es = fmaf(-2.7f, cn0 + cn1, es0 + es1);
#pragma unroll
    for (int o = 16; o > 0; o >>= 1)
        es += __shfl_down_sync(0xffffffffu, es, o);

    __shared__ float wes[BLOCK_T / 32];
    if ((tid & 31) == 0) wes[tid >> 5] = es;
    __syncthreads();

    if (tid == 0) {
        float e = 0.f;
#pragma unroll
        for (int w = 0; w < BLOCK_T / 32; w++) e += wes[w];

        atomicAdd(&g_es, e);
        __threadfence();
        unsigned int t = atomicAdd(&g_ticket, 1u);
        if (t == (unsigned int)(NBLK - 1)) {
            __threadfence();
            *out = *(volatile float*)&g_es;
            g_es = 0.0f;          // reset for next graph replay
            g_ticket = 0u;
        }
    }
}

// ---------------------------------------------------------------------------
extern "C" void kernel_launch(void* const* d_in, const int* in_sizes, int n_in,
                              void* d_out, int out_size)
{
    const float* coords  = (const float*)d_in[0];
    const int*   res_ids = (const int*)  d_in[1];
    const int*   types   = (const int*)  d_in[2];
    const float* pot     = (const float*)d_in[3];
    float*       out     = (float*)d_out;

    int n = in_sizes[1];
    if (n > N_MAX) n = N_MAX;

    pack_kernel<<<N_MAX / 128, 128>>>(coords, res_ids, types, n);
    scatter_kernel<<<N_MAX / 128, 128>>>();

    dim3 grid(NWORK, 2);
    pair_kernel<<<grid, BLOCK_T>>>(pot, out);
}